// round 13
// baseline (speedup 1.0000x reference)
#include <cuda_runtime.h>

#define BB 512
#define TT 1024
#define IDIM 64
#define HH 10
#define G4 40   // 4*H

typedef unsigned long long u64;

// Scratch (static device globals — no runtime allocation)
// XG layout per row: unit-interleaved pairs, u64 index p2 (0..19):
//   p2 = 2k   -> (i_k, f_k) preacts, PRE-SCALED by 0.5
//   p2 = 2k+1 -> (g_k, o_k) preacts, g unscaled, o PRE-SCALED by 0.5
__device__ float d_XG1[BB * TT * G4];
__device__ float d_XG2[BB * TT * G4];
__device__ float d_h1T[BB * HH];   // stores hbig = 2*h
__device__ float d_c1T[BB * HH];

// position p = 4*u + gt (gt: 0=i,1=f,2=g,3=o) -> original PyTorch gate row
__device__ __forceinline__ int old_gate(int p) {
    int u = p >> 2, gt = p & 3;
    return gt * HH + u;
}

__device__ __forceinline__ float tanh_ap(float x) {
    float y;
    asm("tanh.approx.f32 %0, %1;" : "=f"(y) : "f"(x));
    return y;
}

// ---- packed f32x2 helpers (sm_100+) ----
__device__ __forceinline__ u64 pk2(float lo, float hi) {
    u64 r; asm("mov.b64 %0, {%1, %2};" : "=l"(r) : "f"(lo), "f"(hi)); return r;
}
__device__ __forceinline__ void upk2(float& lo, float& hi, u64 v) {
    asm("mov.b64 {%0, %1}, %2;" : "=f"(lo), "=f"(hi) : "l"(v));
}
__device__ __forceinline__ u64 fma2(u64 a, u64 b, u64 c) {
    u64 d; asm("fma.rn.f32x2 %0, %1, %2, %3;" : "=l"(d) : "l"(a), "l"(b), "l"(c)); return d;
}
__device__ __forceinline__ u64 mul2(u64 a, u64 b) {
    u64 d; asm("mul.rn.f32x2 %0, %1, %2;" : "=l"(d) : "l"(a), "l"(b)); return d;
}
__device__ __forceinline__ u64 add2(u64 a, u64 b) {
    u64 d; asm("add.rn.f32x2 %0, %1, %2;" : "=l"(d) : "l"(a), "l"(b)); return d;
}

// ---------------------------------------------------------------------------
// K1 (FROZEN — measured 98us): input GEMM -> d_XG1, folded scales.
// ---------------------------------------------------------------------------
__global__ __launch_bounds__(256) void k_inputgemm(
    const float* __restrict__ x,      // [B*T, 64]
    const float* __restrict__ W,      // [40, 64] (orig gate order)
    const float* __restrict__ b1,
    const float* __restrict__ b2)
{
    __shared__ u64 sW[64 * 20];
    __shared__ u64 sB[20];
    int tid = threadIdx.x;
    for (int e = tid; e < 64 * 20; e += 256) {
        int k = e / 20, p2 = e % 20;
        float slo = (p2 & 1) ? 1.0f : 0.5f;
        float lo = slo * W[old_gate(2 * p2) * 64 + k];
        float hi = 0.5f * W[old_gate(2 * p2 + 1) * 64 + k];
        sW[e] = pk2(lo, hi);
    }
    for (int e = tid; e < 20; e += 256) {
        int p2 = e;
        float slo = (p2 & 1) ? 1.0f : 0.5f;
        int oA = old_gate(2 * p2), oB = old_gate(2 * p2 + 1);
        sB[e] = pk2(slo * (b1[oA] + b2[oA]), 0.5f * (b1[oB] + b2[oB]));
    }
    __syncthreads();

    int gt = blockIdx.x * 256 + tid;
    int rowblk = gt >> 2;
    int q = gt & 3;
    size_t r0 = (size_t)rowblk * 8;

    u64 acc[8][5];
#pragma unroll
    for (int r = 0; r < 8; r++)
#pragma unroll
        for (int j = 0; j < 5; j++) acc[r][j] = sB[q + 4 * j];

    const float4* x4 = reinterpret_cast<const float4*>(x);
#pragma unroll 2
    for (int kk = 0; kk < 16; kk++) {
        float4 xv[8];
#pragma unroll
        for (int r = 0; r < 8; r++) xv[r] = x4[(r0 + r) * 16 + kk];
#pragma unroll
        for (int c = 0; c < 4; c++) {
            u64 xd[8];
#pragma unroll
            for (int r = 0; r < 8; r++) {
                float xc = (c == 0) ? xv[r].x : (c == 1) ? xv[r].y
                         : (c == 2) ? xv[r].z : xv[r].w;
                xd[r] = pk2(xc, xc);
            }
#pragma unroll
            for (int j = 0; j < 5; j++) {
                u64 w = sW[(4 * kk + c) * 20 + q + 4 * j];
#pragma unroll
                for (int r = 0; r < 8; r++)
                    acc[r][j] = fma2(w, xd[r], acc[r][j]);
            }
        }
    }
#pragma unroll
    for (int r = 0; r < 8; r++) {
        u64* orow = reinterpret_cast<u64*>(d_XG1 + (r0 + r) * G4);
#pragma unroll
        for (int j = 0; j < 5; j++) orow[q + 4 * j] = acc[r][j];
    }
}

// ---------------------------------------------------------------------------
// lstm1 (FROZEN — R12-proven): role-shared trees, single chain, fused xg2.
// ---------------------------------------------------------------------------
#define STEP1(hb, cc, hv, ab, outp, sidx)                                     \
    {                                                                         \
        u64 t1 = gemmrole ? bIF : (ab).x;                                     \
        u64 t2 = gemmrole ? bGO : (ab).y;                                     \
        u64 e1 = fma2(wa[0], hv[0], t1);                                      \
        e1 = fma2(wa[2], hv[2], e1);                                          \
        e1 = fma2(wa[4], hv[4], e1);                                          \
        e1 = fma2(wa[6], hv[6], e1);                                          \
        e1 = fma2(wa[8], hv[8], e1);                                          \
        u64 o1 = mul2(wa[1], hv[1]);                                          \
        o1 = fma2(wa[3], hv[3], o1);                                          \
        o1 = fma2(wa[5], hv[5], o1);                                          \
        o1 = fma2(wa[7], hv[7], o1);                                          \
        o1 = fma2(wa[9], hv[9], o1);                                          \
        u64 g1 = add2(e1, o1);                                                \
        u64 e2 = fma2(wb[0], hv[0], t2);                                      \
        e2 = fma2(wb[2], hv[2], e2);                                          \
        e2 = fma2(wb[4], hv[4], e2);                                          \
        e2 = fma2(wb[6], hv[6], e2);                                          \
        e2 = fma2(wb[8], hv[8], e2);                                          \
        u64 o2 = mul2(wb[1], hv[1]);                                          \
        o2 = fma2(wb[3], hv[3], o2);                                          \
        o2 = fma2(wb[5], hv[5], o2);                                          \
        o2 = fma2(wb[7], hv[7], o2);                                          \
        o2 = fma2(wb[9], hv[9], o2);                                          \
        u64 g2 = add2(e2, o2);                                                \
        if (gemmrole && (sidx) >= 0) {                                        \
            ulonglong2 v; v.x = g1; v.y = g2;                                 \
            (outp)[(size_t)(sidx) * HH] = v;                                  \
        }                                                                     \
        float xi, xf, xg, xo;                                                 \
        upk2(xi, xf, g1);                                                     \
        upk2(xg, xo, g2);                                                     \
        float ti = tanh_ap(xi);                                               \
        float tf = tanh_ap(xf);                                               \
        float tg = tanh_ap(xg);                                               \
        float to_ = tanh_ap(xo);                                              \
        float u_ = fmaf(tf, cc, cc);                                          \
        float v_ = fmaf(ti, tg, tg);                                          \
        cc = 0.5f * (u_ + v_);                                                \
        float tc = tanh_ap(cc);                                               \
        hb = fmaf(to_, tc, tc);                                               \
        _Pragma("unroll")                                                     \
        for (int j = 0; j < 10; j++) {                                        \
            float hj = __shfl_sync(0xffffffffu, hb, j);                       \
            hv[j] = pk2(hj, hj);                                              \
        }                                                                     \
    }

#define GEMM_TAIL(hv, outp)                                                   \
    {                                                                         \
        u64 e1 = fma2(wa[0], hv[0], bIF);                                     \
        e1 = fma2(wa[2], hv[2], e1);                                          \
        e1 = fma2(wa[4], hv[4], e1);                                          \
        e1 = fma2(wa[6], hv[6], e1);                                          \
        e1 = fma2(wa[8], hv[8], e1);                                          \
        u64 o1 = mul2(wa[1], hv[1]);                                          \
        o1 = fma2(wa[3], hv[3], o1);                                          \
        o1 = fma2(wa[5], hv[5], o1);                                          \
        o1 = fma2(wa[7], hv[7], o1);                                          \
        o1 = fma2(wa[9], hv[9], o1);                                          \
        u64 g1 = add2(e1, o1);                                                \
        u64 e2 = fma2(wb[0], hv[0], bGO);                                     \
        e2 = fma2(wb[2], hv[2], e2);                                          \
        e2 = fma2(wb[4], hv[4], e2);                                          \
        e2 = fma2(wb[6], hv[6], e2);                                          \
        e2 = fma2(wb[8], hv[8], e2);                                          \
        u64 o2 = mul2(wb[1], hv[1]);                                          \
        o2 = fma2(wb[3], hv[3], o2);                                          \
        o2 = fma2(wb[5], hv[5], o2);                                          \
        o2 = fma2(wb[7], hv[7], o2);                                          \
        o2 = fma2(wb[9], hv[9], o2);                                          \
        u64 g2 = add2(e2, o2);                                                \
        if (gemmrole) {                                                       \
            ulonglong2 v; v.x = g1; v.y = g2;                                 \
            (outp)[(size_t)(TT - 1) * HH] = v;                                \
        }                                                                     \
    }

__global__ __launch_bounds__(128) void k_lstm1(
    const float* __restrict__ Whh,    // [40,10] layer-1
    const float* __restrict__ h0,
    const float* __restrict__ c0,
    const float* __restrict__ Wih2,   // [40,10]
    const float* __restrict__ bih2,
    const float* __restrict__ bhh2)
{
    int warp = (blockIdx.x * blockDim.x + threadIdx.x) >> 5;  // 512 warps
    int lane = threadIdx.x & 31;
    int k2 = lane % HH;
    bool gemmrole = (lane >= 10 && lane < 20);
    bool klow = lane < HH;

    const float* Wsel = gemmrole ? Wih2 : Whh;
    u64 wa[10], wb[10];
#pragma unroll
    for (int j = 0; j < 10; j++) {
        wa[j] = pk2(0.25f * Wsel[(0 * HH + k2) * HH + j],
                    0.25f * Wsel[(1 * HH + k2) * HH + j]);
        wb[j] = pk2(0.50f * Wsel[(2 * HH + k2) * HH + j],
                    0.25f * Wsel[(3 * HH + k2) * HH + j]);
    }
    u64 bIF = pk2(0.5f * (bih2[0 * HH + k2] + bhh2[0 * HH + k2]),
                  0.5f * (bih2[1 * HH + k2] + bhh2[1 * HH + k2]));
    u64 bGO = pk2(1.0f * (bih2[2 * HH + k2] + bhh2[2 * HH + k2]),
                  0.5f * (bih2[3 * HH + k2] + bhh2[3 * HH + k2]));

    float hb = 2.0f * h0[warp * HH + k2];
    float cc = c0[warp * HH + k2];
    u64 hv[10];
#pragma unroll
    for (int j = 0; j < 10; j++) {
        float hj = __shfl_sync(0xffffffffu, hb, j);
        hv[j] = pk2(hj, hj);
    }

    const ulonglong2* base =
        reinterpret_cast<const ulonglong2*>(d_XG1) + (size_t)warp * TT * HH + k2;
    ulonglong2* outp =
        reinterpret_cast<ulonglong2*>(d_XG2) + (size_t)warp * TT * HH + k2;

    ulonglong2 cur[4], nxt[4];
#pragma unroll
    for (int i = 0; i < 4; i++) cur[i] = base[i * HH];
#pragma unroll
    for (int i = 0; i < 4; i++) nxt[i] = base[(4 + i) * HH];

    for (int t = 0; t < TT; t += 4) {
        ulonglong2 pf[4];
        if (t + 8 < TT) {
#pragma unroll
            for (int i = 0; i < 4; i++) pf[i] = base[(size_t)(t + 8 + i) * HH];
        }
#pragma unroll
        for (int s = 0; s < 4; s++) {
            STEP1(hb, cc, hv, cur[s], outp, t + s - 1);
        }
#pragma unroll
        for (int i = 0; i < 4; i++) { cur[i] = nxt[i]; nxt[i] = pf[i]; }
    }
    GEMM_TAIL(hv, outp);

    if (klow) {
        d_h1T[warp * HH + k2] = hb;
        d_c1T[warp * HH + k2] = cc;
    }
}

// ---------------------------------------------------------------------------
// lstm2 (NEW): split-reduction "halves" step.
// Lane (g = lane&15, half = lane>>4), unit k2 = g%10, h-columns [5*half,5*half+5).
// Each lane computes PARTIAL gate sums over its 5 columns; butterfly
// shfl_xor(16) combines halves so ALL lanes hold full gates -> consistent
// cc/hb everywhere. Broadcast needs only 5 shfls (src = 5*half + j, always a
// lane in 0..9). Duplicate lanes (g>=10) are masked out of the FC reduce.
// ---------------------------------------------------------------------------
#define STEP2H(hb, cc, hv, ab)                                                \
    {                                                                         \
        u64 baseIF = half ? 0ull : (ab).x;                                    \
        u64 baseGO = half ? 0ull : (ab).y;                                    \
        u64 pIF = fma2(wa[0], hv[0], baseIF);                                 \
        pIF = fma2(wa[1], hv[1], pIF);                                        \
        pIF = fma2(wa[2], hv[2], pIF);                                        \
        pIF = fma2(wa[3], hv[3], pIF);                                        \
        pIF = fma2(wa[4], hv[4], pIF);                                        \
        u64 pGO = fma2(wb[0], hv[0], baseGO);                                 \
        pGO = fma2(wb[1], hv[1], pGO);                                        \
        pGO = fma2(wb[2], hv[2], pGO);                                        \
        pGO = fma2(wb[3], hv[3], pGO);                                        \
        pGO = fma2(wb[4], hv[4], pGO);                                        \
        float xi, xf, xg, xo;                                                 \
        upk2(xi, xf, pIF);                                                    \
        upk2(xg, xo, pGO);                                                    \
        xi += __shfl_xor_sync(0xffffffffu, xi, 16);                           \
        xf += __shfl_xor_sync(0xffffffffu, xf, 16);                           \
        xg += __shfl_xor_sync(0xffffffffu, xg, 16);                           \
        xo += __shfl_xor_sync(0xffffffffu, xo, 16);                           \
        float ti = tanh_ap(xi);                                               \
        float tf = tanh_ap(xf);                                               \
        float tg = tanh_ap(xg);                                               \
        float to_ = tanh_ap(xo);                                              \
        float u_ = fmaf(tf, cc, cc);                                          \
        float v_ = fmaf(ti, tg, tg);                                          \
        cc = 0.5f * (u_ + v_);                                                \
        float tc = tanh_ap(cc);                                               \
        hb = fmaf(to_, tc, tc);                                               \
        _Pragma("unroll")                                                     \
        for (int j = 0; j < 5; j++) {                                         \
            float hj = __shfl_sync(0xffffffffu, hb, col0 + j);                \
            hv[j] = pk2(hj, hj);                                              \
        }                                                                     \
    }

__global__ __launch_bounds__(128) void k_lstm2(
    const float* __restrict__ Whh,    // [40,10] layer-2
    const float* __restrict__ fc1w,
    const float* __restrict__ fc1b,
    const float* __restrict__ fc2w,   // [1024]
    const float* __restrict__ fc2b,
    float* __restrict__ out)
{
    int warp = (blockIdx.x * blockDim.x + threadIdx.x) >> 5;  // 512 warps
    int lane = threadIdx.x & 31;
    int g = lane & 15;
    int half = lane >> 4;
    int k2 = g % HH;
    int col0 = 5 * half;
    bool klow = lane < HH;            // half0, g<10: unique contributors

    // 5 weight columns (this lane's h-half), folded scales
    u64 wa[5], wb[5];
#pragma unroll
    for (int j = 0; j < 5; j++) {
        wa[j] = pk2(0.25f * Whh[(0 * HH + k2) * HH + col0 + j],
                    0.25f * Whh[(1 * HH + k2) * HH + col0 + j]);
        wb[j] = pk2(0.50f * Whh[(2 * HH + k2) * HH + col0 + j],
                    0.25f * Whh[(3 * HH + k2) * HH + col0 + j]);
    }

    float hb = d_h1T[warp * HH + k2];   // hbig
    float cc = d_c1T[warp * HH + k2];
    u64 hv[5];
#pragma unroll
    for (int j = 0; j < 5; j++) {
        float hj = __shfl_sync(0xffffffffu, hb, col0 + j);
        hv[j] = pk2(hj, hj);
    }

    const ulonglong2* base =
        reinterpret_cast<const ulonglong2*>(d_XG2) + (size_t)warp * TT * HH + k2;
    const float4* f4 = reinterpret_cast<const float4*>(fc2w);

    ulonglong2 cur[4], nxt[4];
#pragma unroll
    for (int i = 0; i < 4; i++) cur[i] = base[i * HH];
#pragma unroll
    for (int i = 0; i < 4; i++) nxt[i] = base[(4 + i) * HH];

    float acc = 0.0f;   // sum_t hbig * fc2w[t]
    float s2 = 0.0f;    // sum_t fc2w[t]

    for (int t = 0; t < TT; t += 4) {
        ulonglong2 pf[4];
        if (t + 8 < TT) {
#pragma unroll
            for (int i = 0; i < 4; i++) pf[i] = base[(size_t)(t + 8 + i) * HH];
        }
        float4 fwv = __ldg(&f4[t >> 2]);
        float fw4[4] = {fwv.x, fwv.y, fwv.z, fwv.w};
#pragma unroll
        for (int s = 0; s < 4; s++) {
            STEP2H(hb, cc, hv, cur[s]);
            acc = fmaf(hb, fw4[s], acc);
            s2 += fw4[s];
        }
#pragma unroll
        for (int i = 0; i < 4; i++) { cur[i] = nxt[i]; nxt[i] = pf[i]; }
    }

    // acc holds 2*sum(h*fw) -> scale fc1w by 0.5; only lanes 0-9 contribute.
    float val = klow ? acc * (0.5f * fc1w[k2]) : 0.0f;
#pragma unroll
    for (int off = 16; off > 0; off >>= 1)
        val += __shfl_xor_sync(0xffffffffu, val, off);
    if (lane == 0)
        out[warp] = val + fc1b[0] * s2 + fc2b[0];
}

// ---------------------------------------------------------------------------
extern "C" void kernel_launch(void* const* d_in, const int* in_sizes, int n_in,
                              void* d_out, int out_size)
{
    const float* x    = (const float*)d_in[0];
    const float* h0   = (const float*)d_in[1];
    const float* c0   = (const float*)d_in[2];
    const float* Wih1 = (const float*)d_in[3];
    const float* Whh1 = (const float*)d_in[4];
    const float* bih1 = (const float*)d_in[5];
    const float* bhh1 = (const float*)d_in[6];
    const float* Wih2 = (const float*)d_in[7];
    const float* Whh2 = (const float*)d_in[8];
    const float* bih2 = (const float*)d_in[9];
    const float* bhh2 = (const float*)d_in[10];
    const float* fc1w = (const float*)d_in[11];
    const float* fc1b = (const float*)d_in[12];
    const float* fc2w = (const float*)d_in[13];
    const float* fc2b = (const float*)d_in[14];
    float* out = (float*)d_out;

    k_inputgemm<<<1024, 256>>>(x, Wih1, bih1, bhh1);        // FROZEN (98us)
    k_lstm1<<<128, 128>>>(Whh1, h0, c0, Wih2, bih2, bhh2);  // FROZEN (R12)
    k_lstm2<<<128, 128>>>(Whh2, fc1w, fc1b, fc2w, fc2b, out); // NEW halves-split
}

// round 14
// speedup vs baseline: 1.0414x; 1.0414x over previous
#include <cuda_runtime.h>

#define BB 512
#define TT 1024
#define IDIM 64
#define HH 10
#define G4 40   // 4*H

typedef unsigned long long u64;

// Scratch (static device globals — no runtime allocation)
// XG layout per row: unit-interleaved pairs, u64 index p2 (0..19):
//   p2 = 2k   -> (i_k, f_k) preacts, PRE-SCALED by 0.5
//   p2 = 2k+1 -> (g_k, o_k) preacts, g unscaled, o PRE-SCALED by 0.5
__device__ float d_XG1[BB * TT * G4];
__device__ float d_XG2[BB * TT * G4];
__device__ float d_h1T[BB * HH];   // stores hbig = 2*h
__device__ float d_c1T[BB * HH];

// position p = 4*u + gt (gt: 0=i,1=f,2=g,3=o) -> original PyTorch gate row
__device__ __forceinline__ int old_gate(int p) {
    int u = p >> 2, gt = p & 3;
    return gt * HH + u;
}

__device__ __forceinline__ float tanh_ap(float x) {
    float y;
    asm("tanh.approx.f32 %0, %1;" : "=f"(y) : "f"(x));
    return y;
}

// ---- packed f32x2 helpers (sm_100+) ----
__device__ __forceinline__ u64 pk2(float lo, float hi) {
    u64 r; asm("mov.b64 %0, {%1, %2};" : "=l"(r) : "f"(lo), "f"(hi)); return r;
}
__device__ __forceinline__ void upk2(float& lo, float& hi, u64 v) {
    asm("mov.b64 {%0, %1}, %2;" : "=f"(lo), "=f"(hi) : "l"(v));
}
__device__ __forceinline__ u64 fma2(u64 a, u64 b, u64 c) {
    u64 d; asm("fma.rn.f32x2 %0, %1, %2, %3;" : "=l"(d) : "l"(a), "l"(b), "l"(c)); return d;
}
__device__ __forceinline__ u64 mul2(u64 a, u64 b) {
    u64 d; asm("mul.rn.f32x2 %0, %1, %2;" : "=l"(d) : "l"(a), "l"(b)); return d;
}
__device__ __forceinline__ u64 add2(u64 a, u64 b) {
    u64 d; asm("add.rn.f32x2 %0, %1, %2;" : "=l"(d) : "l"(a), "l"(b)); return d;
}

// ---------------------------------------------------------------------------
// K1 (NEW): smem-staged input GEMM -> d_XG1, folded scales.
// Block owns a 128-row x tile; load phase fully coalesced; compute reads from
// smem (pitch 17 float4 = 272B; thread rows rs and rs+64 -> the 8 distinct
// rows per warp-load map to distinct banks). Thread = 2 rows x 5 gate-pairs.
// ---------------------------------------------------------------------------
#define ROWS_PB 128
#define XPITCH 17   // float4 per row (16 data + 1 pad)

__global__ __launch_bounds__(256) void k_inputgemm(
    const float* __restrict__ x,      // [B*T, 64]
    const float* __restrict__ W,      // [40, 64] (orig gate order)
    const float* __restrict__ b1,
    const float* __restrict__ b2)
{
    __shared__ float4 sX[ROWS_PB * XPITCH];   // 34816 B
    __shared__ u64 sW[64 * 20];               // 10240 B
    __shared__ u64 sB[20];
    int tid = threadIdx.x;
    for (int e = tid; e < 64 * 20; e += 256) {
        int k = e / 20, p2 = e % 20;
        float slo = (p2 & 1) ? 1.0f : 0.5f;
        float lo = slo * W[old_gate(2 * p2) * 64 + k];
        float hi = 0.5f * W[old_gate(2 * p2 + 1) * 64 + k];
        sW[e] = pk2(lo, hi);
    }
    for (int e = tid; e < 20; e += 256) {
        float slo = (e & 1) ? 1.0f : 0.5f;
        int oA = old_gate(2 * e), oB = old_gate(2 * e + 1);
        sB[e] = pk2(slo * (b1[oA] + b2[oA]), 0.5f * (b1[oB] + b2[oB]));
    }

    size_t rowBase = (size_t)blockIdx.x * ROWS_PB;
    const float4* x4 = reinterpret_cast<const float4*>(x) + rowBase * 16;
#pragma unroll
    for (int i = 0; i < 8; i++) {
        int idx = i * 256 + tid;      // 0..2047, coalesced
        int row = idx >> 4, col = idx & 15;
        sX[row * XPITCH + col] = x4[idx];
    }
    __syncthreads();

    int q = tid & 3;
    int rs = tid >> 2;                // 0..63; rows rs and rs+64

    u64 acc[2][5];
#pragma unroll
    for (int r = 0; r < 2; r++)
#pragma unroll
        for (int j = 0; j < 5; j++) acc[r][j] = sB[q + 4 * j];

#pragma unroll 4
    for (int kk = 0; kk < 16; kk++) {
        float4 xv0 = sX[rs * XPITCH + kk];
        float4 xv1 = sX[(rs + 64) * XPITCH + kk];
#pragma unroll
        for (int c = 0; c < 4; c++) {
            float a0 = (c == 0) ? xv0.x : (c == 1) ? xv0.y : (c == 2) ? xv0.z : xv0.w;
            float a1 = (c == 0) ? xv1.x : (c == 1) ? xv1.y : (c == 2) ? xv1.z : xv1.w;
            u64 xd0 = pk2(a0, a0);
            u64 xd1 = pk2(a1, a1);
#pragma unroll
            for (int j = 0; j < 5; j++) {
                u64 w = sW[(4 * kk + c) * 20 + q + 4 * j];
                acc[0][j] = fma2(w, xd0, acc[0][j]);
                acc[1][j] = fma2(w, xd1, acc[1][j]);
            }
        }
    }
#pragma unroll
    for (int r = 0; r < 2; r++) {
        size_t grow = rowBase + rs + (size_t)r * 64;
        u64* orow = reinterpret_cast<u64*>(d_XG1 + grow * G4);
#pragma unroll
        for (int j = 0; j < 5; j++) orow[q + 4 * j] = acc[r][j];
    }
}

// ---------------------------------------------------------------------------
// lstm1 (FROZEN — R12-proven, 440us config): role-shared trees, single chain.
// ---------------------------------------------------------------------------
#define STEP1(hb, cc, hv, ab, outp, sidx)                                     \
    {                                                                         \
        u64 t1 = gemmrole ? bIF : (ab).x;                                     \
        u64 t2 = gemmrole ? bGO : (ab).y;                                     \
        u64 e1 = fma2(wa[0], hv[0], t1);                                      \
        e1 = fma2(wa[2], hv[2], e1);                                          \
        e1 = fma2(wa[4], hv[4], e1);                                          \
        e1 = fma2(wa[6], hv[6], e1);                                          \
        e1 = fma2(wa[8], hv[8], e1);                                          \
        u64 o1 = mul2(wa[1], hv[1]);                                          \
        o1 = fma2(wa[3], hv[3], o1);                                          \
        o1 = fma2(wa[5], hv[5], o1);                                          \
        o1 = fma2(wa[7], hv[7], o1);                                          \
        o1 = fma2(wa[9], hv[9], o1);                                          \
        u64 g1 = add2(e1, o1);                                                \
        u64 e2 = fma2(wb[0], hv[0], t2);                                      \
        e2 = fma2(wb[2], hv[2], e2);                                          \
        e2 = fma2(wb[4], hv[4], e2);                                          \
        e2 = fma2(wb[6], hv[6], e2);                                          \
        e2 = fma2(wb[8], hv[8], e2);                                          \
        u64 o2 = mul2(wb[1], hv[1]);                                          \
        o2 = fma2(wb[3], hv[3], o2);                                          \
        o2 = fma2(wb[5], hv[5], o2);                                          \
        o2 = fma2(wb[7], hv[7], o2);                                          \
        o2 = fma2(wb[9], hv[9], o2);                                          \
        u64 g2 = add2(e2, o2);                                                \
        if (gemmrole && (sidx) >= 0) {                                        \
            ulonglong2 v; v.x = g1; v.y = g2;                                 \
            (outp)[(size_t)(sidx) * HH] = v;                                  \
        }                                                                     \
        float xi, xf, xg, xo;                                                 \
        upk2(xi, xf, g1);                                                     \
        upk2(xg, xo, g2);                                                     \
        float ti = tanh_ap(xi);                                               \
        float tf = tanh_ap(xf);                                               \
        float tg = tanh_ap(xg);                                               \
        float to_ = tanh_ap(xo);                                              \
        float u_ = fmaf(tf, cc, cc);                                          \
        float v_ = fmaf(ti, tg, tg);                                          \
        cc = 0.5f * (u_ + v_);                                                \
        float tc = tanh_ap(cc);                                               \
        hb = fmaf(to_, tc, tc);                                               \
        _Pragma("unroll")                                                     \
        for (int j = 0; j < 10; j++) {                                        \
            float hj = __shfl_sync(0xffffffffu, hb, j);                       \
            hv[j] = pk2(hj, hj);                                              \
        }                                                                     \
    }

#define GEMM_TAIL(hv, outp)                                                   \
    {                                                                         \
        u64 e1 = fma2(wa[0], hv[0], bIF);                                     \
        e1 = fma2(wa[2], hv[2], e1);                                          \
        e1 = fma2(wa[4], hv[4], e1);                                          \
        e1 = fma2(wa[6], hv[6], e1);                                          \
        e1 = fma2(wa[8], hv[8], e1);                                          \
        u64 o1 = mul2(wa[1], hv[1]);                                          \
        o1 = fma2(wa[3], hv[3], o1);                                          \
        o1 = fma2(wa[5], hv[5], o1);                                          \
        o1 = fma2(wa[7], hv[7], o1);                                          \
        o1 = fma2(wa[9], hv[9], o1);                                          \
        u64 g1 = add2(e1, o1);                                                \
        u64 e2 = fma2(wb[0], hv[0], bGO);                                     \
        e2 = fma2(wb[2], hv[2], e2);                                          \
        e2 = fma2(wb[4], hv[4], e2);                                          \
        e2 = fma2(wb[6], hv[6], e2);                                          \
        e2 = fma2(wb[8], hv[8], e2);                                          \
        u64 o2 = mul2(wb[1], hv[1]);                                          \
        o2 = fma2(wb[3], hv[3], o2);                                          \
        o2 = fma2(wb[5], hv[5], o2);                                          \
        o2 = fma2(wb[7], hv[7], o2);                                          \
        o2 = fma2(wb[9], hv[9], o2);                                          \
        u64 g2 = add2(e2, o2);                                                \
        if (gemmrole) {                                                       \
            ulonglong2 v; v.x = g1; v.y = g2;                                 \
            (outp)[(size_t)(TT - 1) * HH] = v;                                \
        }                                                                     \
    }

__global__ __launch_bounds__(128) void k_lstm1(
    const float* __restrict__ Whh,    // [40,10] layer-1
    const float* __restrict__ h0,
    const float* __restrict__ c0,
    const float* __restrict__ Wih2,   // [40,10]
    const float* __restrict__ bih2,
    const float* __restrict__ bhh2)
{
    int warp = (blockIdx.x * blockDim.x + threadIdx.x) >> 5;  // 512 warps
    int lane = threadIdx.x & 31;
    int k2 = lane % HH;
    bool gemmrole = (lane >= 10 && lane < 20);
    bool klow = lane < HH;

    const float* Wsel = gemmrole ? Wih2 : Whh;
    u64 wa[10], wb[10];
#pragma unroll
    for (int j = 0; j < 10; j++) {
        wa[j] = pk2(0.25f * Wsel[(0 * HH + k2) * HH + j],
                    0.25f * Wsel[(1 * HH + k2) * HH + j]);
        wb[j] = pk2(0.50f * Wsel[(2 * HH + k2) * HH + j],
                    0.25f * Wsel[(3 * HH + k2) * HH + j]);
    }
    u64 bIF = pk2(0.5f * (bih2[0 * HH + k2] + bhh2[0 * HH + k2]),
                  0.5f * (bih2[1 * HH + k2] + bhh2[1 * HH + k2]));
    u64 bGO = pk2(1.0f * (bih2[2 * HH + k2] + bhh2[2 * HH + k2]),
                  0.5f * (bih2[3 * HH + k2] + bhh2[3 * HH + k2]));

    float hb = 2.0f * h0[warp * HH + k2];
    float cc = c0[warp * HH + k2];
    u64 hv[10];
#pragma unroll
    for (int j = 0; j < 10; j++) {
        float hj = __shfl_sync(0xffffffffu, hb, j);
        hv[j] = pk2(hj, hj);
    }

    const ulonglong2* base =
        reinterpret_cast<const ulonglong2*>(d_XG1) + (size_t)warp * TT * HH + k2;
    ulonglong2* outp =
        reinterpret_cast<ulonglong2*>(d_XG2) + (size_t)warp * TT * HH + k2;

    ulonglong2 cur[4], nxt[4];
#pragma unroll
    for (int i = 0; i < 4; i++) cur[i] = base[i * HH];
#pragma unroll
    for (int i = 0; i < 4; i++) nxt[i] = base[(4 + i) * HH];

    for (int t = 0; t < TT; t += 4) {
        ulonglong2 pf[4];
        if (t + 8 < TT) {
#pragma unroll
            for (int i = 0; i < 4; i++) pf[i] = base[(size_t)(t + 8 + i) * HH];
        }
#pragma unroll
        for (int s = 0; s < 4; s++) {
            STEP1(hb, cc, hv, cur[s], outp, t + s - 1);
        }
#pragma unroll
        for (int i = 0; i < 4; i++) { cur[i] = nxt[i]; nxt[i] = pf[i]; }
    }
    GEMM_TAIL(hv, outp);

    if (klow) {
        d_h1T[warp * HH + k2] = hb;
        d_c1T[warp * HH + k2] = cc;
    }
}

// ---------------------------------------------------------------------------
// lstm2 (REVERTED to R12-proven form): single chain, 4-step unroll, fused FC.
// ---------------------------------------------------------------------------
#define STEP2(hb, cc, hv, ab)                                                 \
    {                                                                         \
        u64 e1 = fma2(wa[0], hv[0], (ab).x);                                  \
        e1 = fma2(wa[2], hv[2], e1);                                          \
        e1 = fma2(wa[4], hv[4], e1);                                          \
        e1 = fma2(wa[6], hv[6], e1);                                          \
        e1 = fma2(wa[8], hv[8], e1);                                          \
        u64 o1 = mul2(wa[1], hv[1]);                                          \
        o1 = fma2(wa[3], hv[3], o1);                                          \
        o1 = fma2(wa[5], hv[5], o1);                                          \
        o1 = fma2(wa[7], hv[7], o1);                                          \
        o1 = fma2(wa[9], hv[9], o1);                                          \
        u64 g1 = add2(e1, o1);                                                \
        u64 e2 = fma2(wb[0], hv[0], (ab).y);                                  \
        e2 = fma2(wb[2], hv[2], e2);                                          \
        e2 = fma2(wb[4], hv[4], e2);                                          \
        e2 = fma2(wb[6], hv[6], e2);                                          \
        e2 = fma2(wb[8], hv[8], e2);                                          \
        u64 o2 = mul2(wb[1], hv[1]);                                          \
        o2 = fma2(wb[3], hv[3], o2);                                          \
        o2 = fma2(wb[5], hv[5], o2);                                          \
        o2 = fma2(wb[7], hv[7], o2);                                          \
        o2 = fma2(wb[9], hv[9], o2);                                          \
        u64 g2 = add2(e2, o2);                                                \
        float xi, xf, xg, xo;                                                 \
        upk2(xi, xf, g1);                                                     \
        upk2(xg, xo, g2);                                                     \
        float ti = tanh_ap(xi);                                               \
        float tf = tanh_ap(xf);                                               \
        float tg = tanh_ap(xg);                                               \
        float to_ = tanh_ap(xo);                                              \
        float u_ = fmaf(tf, cc, cc);                                          \
        float v_ = fmaf(ti, tg, tg);                                          \
        cc = 0.5f * (u_ + v_);                                                \
        float tc = tanh_ap(cc);                                               \
        hb = fmaf(to_, tc, tc);                                               \
        _Pragma("unroll")                                                     \
        for (int j = 0; j < 10; j++) {                                        \
            float hj = __shfl_sync(0xffffffffu, hb, j);                       \
            hv[j] = pk2(hj, hj);                                              \
        }                                                                     \
    }

__global__ __launch_bounds__(128) void k_lstm2(
    const float* __restrict__ Whh,    // [40,10] layer-2
    const float* __restrict__ fc1w,
    const float* __restrict__ fc1b,
    const float* __restrict__ fc2w,   // [1024]
    const float* __restrict__ fc2b,
    float* __restrict__ out)
{
    int warp = (blockIdx.x * blockDim.x + threadIdx.x) >> 5;  // 512 warps
    int lane = threadIdx.x & 31;
    int k2 = lane % HH;
    bool klow = lane < HH;

    u64 wa[10], wb[10];
#pragma unroll
    for (int j = 0; j < 10; j++) {
        wa[j] = pk2(0.25f * Whh[(0 * HH + k2) * HH + j],
                    0.25f * Whh[(1 * HH + k2) * HH + j]);
        wb[j] = pk2(0.50f * Whh[(2 * HH + k2) * HH + j],
                    0.25f * Whh[(3 * HH + k2) * HH + j]);
    }

    float hb = d_h1T[warp * HH + k2];
    float cc = d_c1T[warp * HH + k2];
    u64 hv[10];
#pragma unroll
    for (int j = 0; j < 10; j++) {
        float hj = __shfl_sync(0xffffffffu, hb, j);
        hv[j] = pk2(hj, hj);
    }

    const ulonglong2* base =
        reinterpret_cast<const ulonglong2*>(d_XG2) + (size_t)warp * TT * HH + k2;
    const float4* f4 = reinterpret_cast<const float4*>(fc2w);

    ulonglong2 cur[4], nxt[4];
#pragma unroll
    for (int i = 0; i < 4; i++) cur[i] = base[i * HH];
#pragma unroll
    for (int i = 0; i < 4; i++) nxt[i] = base[(4 + i) * HH];

    float acc = 0.0f;   // sum_t hbig * fc2w[t]
    float s2 = 0.0f;    // sum_t fc2w[t]

    for (int t = 0; t < TT; t += 4) {
        ulonglong2 pf[4];
        if (t + 8 < TT) {
#pragma unroll
            for (int i = 0; i < 4; i++) pf[i] = base[(size_t)(t + 8 + i) * HH];
        }
        float4 fwv = __ldg(&f4[t >> 2]);
        float fw4[4] = {fwv.x, fwv.y, fwv.z, fwv.w};
#pragma unroll
        for (int s = 0; s < 4; s++) {
            STEP2(hb, cc, hv, cur[s]);
            acc = fmaf(hb, fw4[s], acc);
            s2 += fw4[s];
        }
#pragma unroll
        for (int i = 0; i < 4; i++) { cur[i] = nxt[i]; nxt[i] = pf[i]; }
    }

    // acc holds 2*sum(h*fw) -> scale fc1w by 0.5; lanes >=10 contribute 0.
    float val = klow ? acc * (0.5f * fc1w[k2]) : 0.0f;
#pragma unroll
    for (int off = 16; off > 0; off >>= 1)
        val += __shfl_xor_sync(0xffffffffu, val, off);
    if (lane == 0)
        out[warp] = val + fc1b[0] * s2 + fc2b[0];
}

// ---------------------------------------------------------------------------
extern "C" void kernel_launch(void* const* d_in, const int* in_sizes, int n_in,
                              void* d_out, int out_size)
{
    const float* x    = (const float*)d_in[0];
    const float* h0   = (const float*)d_in[1];
    const float* c0   = (const float*)d_in[2];
    const float* Wih1 = (const float*)d_in[3];
    const float* Whh1 = (const float*)d_in[4];
    const float* bih1 = (const float*)d_in[5];
    const float* bhh1 = (const float*)d_in[6];
    const float* Wih2 = (const float*)d_in[7];
    const float* Whh2 = (const float*)d_in[8];
    const float* bih2 = (const float*)d_in[9];
    const float* bhh2 = (const float*)d_in[10];
    const float* fc1w = (const float*)d_in[11];
    const float* fc1b = (const float*)d_in[12];
    const float* fc2w = (const float*)d_in[13];
    const float* fc2b = (const float*)d_in[14];
    float* out = (float*)d_out;

    k_inputgemm<<<4096, 256>>>(x, Wih1, bih1, bhh1);        // NEW smem-staged
    k_lstm1<<<128, 128>>>(Whh1, h0, c0, Wih2, bih2, bhh2);  // FROZEN (R12)
    k_lstm2<<<128, 128>>>(Whh2, fc1w, fc1b, fc2w, fc2b, out); // REVERTED (R12)
}

// round 16
// speedup vs baseline: 1.3357x; 1.2825x over previous
#include <cuda_runtime.h>

#define BB 512
#define TT 1024
#define IDIM 64
#define HH 10
#define G4 40      // 4*H
#define NCHUNK 4   // 4 chunks of 256 timesteps per batch
#define NLSTMB 128 // lstm-role blocks (512 warps)

typedef unsigned long long u64;

// Scratch (static device globals — no runtime allocation)
// XG layout per row: unit-interleaved pairs, u64 index p2 (0..19):
//   p2 = 2k   -> (i_k, f_k) preacts, PRE-SCALED by 0.5
//   p2 = 2k+1 -> (g_k, o_k) preacts, g unscaled, o PRE-SCALED by 0.5
__device__ float d_XG1[BB * TT * G4];
__device__ float d_XG2[BB * TT * G4];
__device__ volatile int d_flag[BB * NCHUNK];   // chunk-ready flags

// position p = 4*u + gt (gt: 0=i,1=f,2=g,3=o) -> original PyTorch gate row
__device__ __forceinline__ int old_gate(int p) {
    int u = p >> 2, gt = p & 3;
    return gt * HH + u;
}

__device__ __forceinline__ float tanh_ap(float x) {
    float y;
    asm("tanh.approx.f32 %0, %1;" : "=f"(y) : "f"(x));
    return y;
}

// ---- packed f32x2 helpers (sm_100+) ----
__device__ __forceinline__ u64 pk2(float lo, float hi) {
    u64 r; asm("mov.b64 %0, {%1, %2};" : "=l"(r) : "f"(lo), "f"(hi)); return r;
}
__device__ __forceinline__ void upk2(float& lo, float& hi, u64 v) {
    asm("mov.b64 {%0, %1}, %2;" : "=f"(lo), "=f"(hi) : "l"(v));
}
__device__ __forceinline__ u64 fma2(u64 a, u64 b, u64 c) {
    u64 d; asm("fma.rn.f32x2 %0, %1, %2, %3;" : "=l"(d) : "l"(a), "l"(b), "l"(c)); return d;
}
__device__ __forceinline__ u64 mul2(u64 a, u64 b) {
    u64 d; asm("mul.rn.f32x2 %0, %1, %2;" : "=l"(d) : "l"(a), "l"(b)); return d;
}
__device__ __forceinline__ u64 add2(u64 a, u64 b) {
    u64 d; asm("add.rn.f32x2 %0, %1, %2;" : "=l"(d) : "l"(a), "l"(b)); return d;
}

__device__ __forceinline__ void waitflag(int idx) {
    while (!d_flag[idx]) __nanosleep(64);
    __threadfence();   // acquire: order subsequent XG1 loads after flag
}

// ---------------------------------------------------------------------------
// flag reset (each graph replay)
// ---------------------------------------------------------------------------
__global__ void k_zeroflags() {
    int i = blockIdx.x * blockDim.x + threadIdx.x;
    if (i < BB * NCHUNK) d_flag[i] = 0;
}

// ---------------------------------------------------------------------------
// lstm step macros (R12-proven forms)
// ---------------------------------------------------------------------------
#define STEP1(hb, cc, hv, ab, outp, sidx)                                     \
    {                                                                         \
        u64 t1 = gemmrole ? bIF : (ab).x;                                     \
        u64 t2 = gemmrole ? bGO : (ab).y;                                     \
        u64 e1 = fma2(wa[0], hv[0], t1);                                      \
        e1 = fma2(wa[2], hv[2], e1);                                          \
        e1 = fma2(wa[4], hv[4], e1);                                          \
        e1 = fma2(wa[6], hv[6], e1);                                          \
        e1 = fma2(wa[8], hv[8], e1);                                          \
        u64 o1 = mul2(wa[1], hv[1]);                                          \
        o1 = fma2(wa[3], hv[3], o1);                                          \
        o1 = fma2(wa[5], hv[5], o1);                                          \
        o1 = fma2(wa[7], hv[7], o1);                                          \
        o1 = fma2(wa[9], hv[9], o1);                                          \
        u64 g1 = add2(e1, o1);                                                \
        u64 e2 = fma2(wb[0], hv[0], t2);                                      \
        e2 = fma2(wb[2], hv[2], e2);                                          \
        e2 = fma2(wb[4], hv[4], e2);                                          \
        e2 = fma2(wb[6], hv[6], e2);                                          \
        e2 = fma2(wb[8], hv[8], e2);                                          \
        u64 o2 = mul2(wb[1], hv[1]);                                          \
        o2 = fma2(wb[3], hv[3], o2);                                          \
        o2 = fma2(wb[5], hv[5], o2);                                          \
        o2 = fma2(wb[7], hv[7], o2);                                          \
        o2 = fma2(wb[9], hv[9], o2);                                          \
        u64 g2 = add2(e2, o2);                                                \
        if (gemmrole && (sidx) >= 0) {                                        \
            ulonglong2 v; v.x = g1; v.y = g2;                                 \
            (outp)[(size_t)(sidx) * HH] = v;                                  \
        }                                                                     \
        float xi, xf, xg, xo;                                                 \
        upk2(xi, xf, g1);                                                     \
        upk2(xg, xo, g2);                                                     \
        float ti = tanh_ap(xi);                                               \
        float tf = tanh_ap(xf);                                               \
        float tg = tanh_ap(xg);                                               \
        float to_ = tanh_ap(xo);                                              \
        float u_ = fmaf(tf, cc, cc);                                          \
        float v_ = fmaf(ti, tg, tg);                                          \
        cc = 0.5f * (u_ + v_);                                                \
        float tc = tanh_ap(cc);                                               \
        hb = fmaf(to_, tc, tc);                                               \
        _Pragma("unroll")                                                     \
        for (int j = 0; j < 10; j++) {                                        \
            float hj = __shfl_sync(0xffffffffu, hb, j);                       \
            hv[j] = pk2(hj, hj);                                              \
        }                                                                     \
    }

#define GEMM_TAIL(hv, outp)                                                   \
    {                                                                         \
        u64 e1 = fma2(wa[0], hv[0], bIF);                                     \
        e1 = fma2(wa[2], hv[2], e1);                                          \
        e1 = fma2(wa[4], hv[4], e1);                                          \
        e1 = fma2(wa[6], hv[6], e1);                                          \
        e1 = fma2(wa[8], hv[8], e1);                                          \
        u64 o1 = mul2(wa[1], hv[1]);                                          \
        o1 = fma2(wa[3], hv[3], o1);                                          \
        o1 = fma2(wa[5], hv[5], o1);                                          \
        o1 = fma2(wa[7], hv[7], o1);                                          \
        o1 = fma2(wa[9], hv[9], o1);                                          \
        u64 g1 = add2(e1, o1);                                                \
        u64 e2 = fma2(wb[0], hv[0], bGO);                                     \
        e2 = fma2(wb[2], hv[2], e2);                                          \
        e2 = fma2(wb[4], hv[4], e2);                                          \
        e2 = fma2(wb[6], hv[6], e2);                                          \
        e2 = fma2(wb[8], hv[8], e2);                                          \
        u64 o2 = mul2(wb[1], hv[1]);                                          \
        o2 = fma2(wb[3], hv[3], o2);                                          \
        o2 = fma2(wb[5], hv[5], o2);                                          \
        o2 = fma2(wb[7], hv[7], o2);                                          \
        o2 = fma2(wb[9], hv[9], o2);                                          \
        u64 g2 = add2(e2, o2);                                                \
        if (gemmrole) {                                                       \
            ulonglong2 v; v.x = g1; v.y = g2;                                 \
            (outp)[(size_t)(TT - 1) * HH] = v;                                \
        }                                                                     \
    }

#define STEP2(hb, cc, hv, ab)                                                 \
    {                                                                         \
        u64 e1 = fma2(wa[0], hv[0], (ab).x);                                  \
        e1 = fma2(wa[2], hv[2], e1);                                          \
        e1 = fma2(wa[4], hv[4], e1);                                          \
        e1 = fma2(wa[6], hv[6], e1);                                          \
        e1 = fma2(wa[8], hv[8], e1);                                          \
        u64 o1 = mul2(wa[1], hv[1]);                                          \
        o1 = fma2(wa[3], hv[3], o1);                                          \
        o1 = fma2(wa[5], hv[5], o1);                                          \
        o1 = fma2(wa[7], hv[7], o1);                                          \
        o1 = fma2(wa[9], hv[9], o1);                                          \
        u64 g1 = add2(e1, o1);                                                \
        u64 e2 = fma2(wb[0], hv[0], (ab).y);                                  \
        e2 = fma2(wb[2], hv[2], e2);                                          \
        e2 = fma2(wb[4], hv[4], e2);                                          \
        e2 = fma2(wb[6], hv[6], e2);                                          \
        e2 = fma2(wb[8], hv[8], e2);                                          \
        u64 o2 = mul2(wb[1], hv[1]);                                          \
        o2 = fma2(wb[3], hv[3], o2);                                          \
        o2 = fma2(wb[5], hv[5], o2);                                          \
        o2 = fma2(wb[7], hv[7], o2);                                          \
        o2 = fma2(wb[9], hv[9], o2);                                          \
        u64 g2 = add2(e2, o2);                                                \
        float xi, xf, xg, xo;                                                 \
        upk2(xi, xf, g1);                                                     \
        upk2(xg, xo, g2);                                                     \
        float ti = tanh_ap(xi);                                               \
        float tf = tanh_ap(xf);                                               \
        float tg = tanh_ap(xg);                                               \
        float to_ = tanh_ap(xo);                                              \
        float u_ = fmaf(tf, cc, cc);                                          \
        float v_ = fmaf(ti, tg, tg);                                          \
        cc = 0.5f * (u_ + v_);                                                \
        float tc = tanh_ap(cc);                                               \
        hb = fmaf(to_, tc, tc);                                               \
        _Pragma("unroll")                                                     \
        for (int j = 0; j < 10; j++) {                                        \
            float hj = __shfl_sync(0xffffffffu, hb, j);                       \
            hv[j] = pk2(hj, hj);                                              \
        }                                                                     \
    }

// ---------------------------------------------------------------------------
// Fused kernel. Blocks 0..127: lstm role (4 warps, 1 batch each; both layers
// + FC, h/c carried in registers). Blocks 128..2175: K1 role (quarter-batch
// each, chunk-major order so all batches' chunk 0 lands first; publishes
// d_flag[b*4+c]). K1 blocks never wait -> forward progress guaranteed.
// ---------------------------------------------------------------------------
__global__ __launch_bounds__(128) void k_fused(
    const float* __restrict__ x,      // [B*T, 64]
    const float* __restrict__ Wih1,   // [40, 64]
    const float* __restrict__ bih1,
    const float* __restrict__ bhh1,
    const float* __restrict__ Whh1,   // [40,10]
    const float* __restrict__ h0,
    const float* __restrict__ c0,
    const float* __restrict__ Wih2,   // [40,10]
    const float* __restrict__ bih2,
    const float* __restrict__ bhh2,
    const float* __restrict__ Whh2,   // [40,10]
    const float* __restrict__ fc1w,
    const float* __restrict__ fc1b,
    const float* __restrict__ fc2w,   // [1024]
    const float* __restrict__ fc2b,
    float* __restrict__ out)          // [B]
{
    __shared__ u64 sW[64 * 20];
    __shared__ u64 sB[20];
    int tid = threadIdx.x;

    if (blockIdx.x >= NLSTMB) {
        // ================= K1 role (proven 98us math; 128 thr, 256 rows) ===
        int krank = blockIdx.x - NLSTMB;   // 0..2047
        int chunk = krank >> 9;            // chunk-major: kranks 0..511 = chunk0
        int batch = krank & 511;

        for (int e = tid; e < 64 * 20; e += 128) {
            int k = e / 20, p2 = e % 20;
            float slo = (p2 & 1) ? 1.0f : 0.5f;
            float lo = slo * Wih1[old_gate(2 * p2) * 64 + k];
            float hi = 0.5f * Wih1[old_gate(2 * p2 + 1) * 64 + k];
            sW[e] = pk2(lo, hi);
        }
        for (int e = tid; e < 20; e += 128) {
            float slo = (e & 1) ? 1.0f : 0.5f;
            int oA = old_gate(2 * e), oB = old_gate(2 * e + 1);
            sB[e] = pk2(slo * (bih1[oA] + bhh1[oA]), 0.5f * (bih1[oB] + bhh1[oB]));
        }
        __syncthreads();

        int q = tid & 3;
        int rb = tid >> 2;                 // 0..31 rowblocks of 8
        size_t r0 = (size_t)batch * TT + (size_t)chunk * 256 + (size_t)rb * 8;

        u64 acc[8][5];
#pragma unroll
        for (int r = 0; r < 8; r++)
#pragma unroll
            for (int j = 0; j < 5; j++) acc[r][j] = sB[q + 4 * j];

        const float4* x4 = reinterpret_cast<const float4*>(x);
#pragma unroll 2
        for (int kk = 0; kk < 16; kk++) {
            float4 xv[8];
#pragma unroll
            for (int r = 0; r < 8; r++) xv[r] = x4[(r0 + r) * 16 + kk];
#pragma unroll
            for (int c = 0; c < 4; c++) {
                u64 xd[8];
#pragma unroll
                for (int r = 0; r < 8; r++) {
                    float xc = (c == 0) ? xv[r].x : (c == 1) ? xv[r].y
                             : (c == 2) ? xv[r].z : xv[r].w;
                    xd[r] = pk2(xc, xc);
                }
#pragma unroll
                for (int j = 0; j < 5; j++) {
                    u64 w = sW[(4 * kk + c) * 20 + q + 4 * j];
#pragma unroll
                    for (int r = 0; r < 8; r++)
                        acc[r][j] = fma2(w, xd[r], acc[r][j]);
                }
            }
        }
#pragma unroll
        for (int r = 0; r < 8; r++) {
            u64* orow = reinterpret_cast<u64*>(d_XG1 + (r0 + r) * G4);
#pragma unroll
            for (int j = 0; j < 5; j++) orow[q + 4 * j] = acc[r][j];
        }

        __threadfence();
        __syncthreads();
        if (tid == 0) d_flag[batch * NCHUNK + chunk] = 1;
        return;
    }

    // ================= lstm role: 4 warps, one batch each ==================
    int lane = tid & 31;
    int batch = blockIdx.x * 4 + (tid >> 5);
    int k2 = lane % HH;
    bool gemmrole = (lane >= 10 && lane < 20);
    bool klow = lane < HH;

    // ---- pass 1: layer-1 recurrence + fused layer-2 input gemm ----
    const float* Wsel = gemmrole ? Wih2 : Whh1;
    u64 wa[10], wb[10];
#pragma unroll
    for (int j = 0; j < 10; j++) {
        wa[j] = pk2(0.25f * Wsel[(0 * HH + k2) * HH + j],
                    0.25f * Wsel[(1 * HH + k2) * HH + j]);
        wb[j] = pk2(0.50f * Wsel[(2 * HH + k2) * HH + j],
                    0.25f * Wsel[(3 * HH + k2) * HH + j]);
    }
    u64 bIF = pk2(0.5f * (bih2[0 * HH + k2] + bhh2[0 * HH + k2]),
                  0.5f * (bih2[1 * HH + k2] + bhh2[1 * HH + k2]));
    u64 bGO = pk2(1.0f * (bih2[2 * HH + k2] + bhh2[2 * HH + k2]),
                  0.5f * (bih2[3 * HH + k2] + bhh2[3 * HH + k2]));

    float hb = 2.0f * h0[batch * HH + k2];
    float cc = c0[batch * HH + k2];
    u64 hv[10];
#pragma unroll
    for (int j = 0; j < 10; j++) {
        float hj = __shfl_sync(0xffffffffu, hb, j);
        hv[j] = pk2(hj, hj);
    }

    const ulonglong2* base =
        reinterpret_cast<const ulonglong2*>(d_XG1) + (size_t)batch * TT * HH + k2;
    ulonglong2* outp =
        reinterpret_cast<ulonglong2*>(d_XG2) + (size_t)batch * TT * HH + k2;

    waitflag(batch * NCHUNK);          // chunk 0 ready (covers t<256)

    ulonglong2 cur[4], nxt[4];
#pragma unroll
    for (int i = 0; i < 4; i++) cur[i] = base[i * HH];
#pragma unroll
    for (int i = 0; i < 4; i++) nxt[i] = base[(4 + i) * HH];

    for (int t = 0; t < TT; t += 4) {
        ulonglong2 pf[4];
        if (t + 8 < TT) {
            if (((t + 8) & 255) == 0)
                waitflag(batch * NCHUNK + ((t + 8) >> 8));
#pragma unroll
            for (int i = 0; i < 4; i++) pf[i] = base[(size_t)(t + 8 + i) * HH];
        }
#pragma unroll
        for (int s = 0; s < 4; s++) {
            STEP1(hb, cc, hv, cur[s], outp, t + s - 1);
        }
#pragma unroll
        for (int i = 0; i < 4; i++) { cur[i] = nxt[i]; nxt[i] = pf[i]; }
    }
    GEMM_TAIL(hv, outp);

    __threadfence_block();
    __syncwarp();

    // ---- pass 2: layer-2 recurrence + fused FC (state carried in regs) ----
    // lanes 0-9 hold valid (hb, cc); lanes >=10 hold garbage but are never
    // read (broadcast sources are lanes 0-9; FC reduce masks them).
#pragma unroll
    for (int j = 0; j < 10; j++) {
        wa[j] = pk2(0.25f * Whh2[(0 * HH + k2) * HH + j],
                    0.25f * Whh2[(1 * HH + k2) * HH + j]);
        wb[j] = pk2(0.50f * Whh2[(2 * HH + k2) * HH + j],
                    0.25f * Whh2[(3 * HH + k2) * HH + j]);
    }
#pragma unroll
    for (int j = 0; j < 10; j++) {
        float hj = __shfl_sync(0xffffffffu, hb, j);
        hv[j] = pk2(hj, hj);
    }

    const ulonglong2* base2 =
        reinterpret_cast<const ulonglong2*>(d_XG2) + (size_t)batch * TT * HH + k2;
    const float4* f4 = reinterpret_cast<const float4*>(fc2w);

    ulonglong2 cur2[4], nxt2[4];
#pragma unroll
    for (int i = 0; i < 4; i++) cur2[i] = base2[i * HH];
#pragma unroll
    for (int i = 0; i < 4; i++) nxt2[i] = base2[(4 + i) * HH];

    float acc = 0.0f;   // sum_t hbig * fc2w[t]
    float s2 = 0.0f;    // sum_t fc2w[t]

    for (int t = 0; t < TT; t += 4) {
        ulonglong2 pf[4];
        if (t + 8 < TT) {
#pragma unroll
            for (int i = 0; i < 4; i++) pf[i] = base2[(size_t)(t + 8 + i) * HH];
        }
        float4 fwv = __ldg(&f4[t >> 2]);
        float fw4[4] = {fwv.x, fwv.y, fwv.z, fwv.w};
#pragma unroll
        for (int s = 0; s < 4; s++) {
            STEP2(hb, cc, hv, cur2[s]);
            acc = fmaf(hb, fw4[s], acc);
            s2 += fw4[s];
        }
#pragma unroll
        for (int i = 0; i < 4; i++) { cur2[i] = nxt2[i]; nxt2[i] = pf[i]; }
    }

    // acc holds 2*sum(h*fw) -> scale fc1w by 0.5; lanes >=10 contribute 0.
    float val = klow ? acc * (0.5f * fc1w[k2]) : 0.0f;
#pragma unroll
    for (int off = 16; off > 0; off >>= 1)
        val += __shfl_xor_sync(0xffffffffu, val, off);
    if (lane == 0)
        out[batch] = val + fc1b[0] * s2 + fc2b[0];
}

// ---------------------------------------------------------------------------
extern "C" void kernel_launch(void* const* d_in, const int* in_sizes, int n_in,
                              void* d_out, int out_size)
{
    const float* x    = (const float*)d_in[0];
    const float* h0   = (const float*)d_in[1];
    const float* c0   = (const float*)d_in[2];
    const float* Wih1 = (const float*)d_in[3];
    const float* Whh1 = (const float*)d_in[4];
    const float* bih1 = (const float*)d_in[5];
    const float* bhh1 = (const float*)d_in[6];
    const float* Wih2 = (const float*)d_in[7];
    const float* Whh2 = (const float*)d_in[8];
    const float* bih2 = (const float*)d_in[9];
    const float* bhh2 = (const float*)d_in[10];
    const float* fc1w = (const float*)d_in[11];
    const float* fc1b = (const float*)d_in[12];
    const float* fc2w = (const float*)d_in[13];
    const float* fc2b = (const float*)d_in[14];
    float* out = (float*)d_out;

    k_zeroflags<<<16, 128>>>();
    k_fused<<<NLSTMB + 2048, 128>>>(
        x, Wih1, bih1, bhh1, Whh1, h0, c0,
        Wih2, bih2, bhh2, Whh2, fc1w, fc1b, fc2w, fc2b, out);
}